// round 15
// baseline (speedup 1.0000x reference)
#include <cuda_runtime.h>
#include <cuda_fp16.h>
#include <cstdint>

#define BATCH 64
#define DIM   524288
#define PROJ  8192
#define CVAL  4
#define NSHARD 8
#define BCAPS  128   // per-(shard,bucket) capacity; mean 32, Poisson tail ~1e-40

// ----------------------------- device scratch ------------------------------
__device__ __align__(16) unsigned short g_xh[(size_t)DIM * BATCH]; // fp16 xT[d][b], 64 MB
__device__ __align__(16) unsigned g_entries[(size_t)NSHARD * PROJ * BCAPS]; // 32 MB
__device__ int g_cursor[NSHARD * PROJ];  // zero-init; gather resets after use

// ---------------------------------------------------------------------------
// Kernel 1 (fused, exact R12): every CTA transposes its 64 d-columns AND
// places its own 64 d-rows into the sharded bucket lists.
// ---------------------------------------------------------------------------
__global__ void __launch_bounds__(256)
prep_kernel(const float* __restrict__ x,
            const int* __restrict__ idx, const int* __restrict__ sgn) {
    __shared__ float tile[64][65];

    const int d0 = blockIdx.x * 64;
    const int t  = threadIdx.x;

    // ---- place: threads 0..63, one d each (coalesced int4 reads) ----
    if (t < 64) {
        const int d = d0 + t;
        const int shard = blockIdx.x & (NSHARD - 1);
        const int4 iv = reinterpret_cast<const int4*>(idx)[d];
        const int4 sv = reinterpret_cast<const int4*>(sgn)[d];
        const unsigned rec = (unsigned)d << 1;
        int* cur = g_cursor + shard * PROJ;
        unsigned* ent = g_entries + (size_t)shard * PROJ * BCAPS;
        int p, pos;
        p = iv.x; pos = atomicAdd(&cur[p], 1);
        if (pos < BCAPS) ent[(size_t)p * BCAPS + pos] = rec | sv.x;
        p = iv.y; pos = atomicAdd(&cur[p], 1);
        if (pos < BCAPS) ent[(size_t)p * BCAPS + pos] = rec | sv.y;
        p = iv.z; pos = atomicAdd(&cur[p], 1);
        if (pos < BCAPS) ent[(size_t)p * BCAPS + pos] = rec | sv.z;
        p = iv.w; pos = atomicAdd(&cur[p], 1);
        if (pos < BCAPS) ent[(size_t)p * BCAPS + pos] = rec | sv.w;
    }

    // ---- transpose phase 1: coalesced float4 reads -> smem ----
    {
        const int col = (t & 15) * 4;
        const int b0  = t >> 4;            // 0..15
        #pragma unroll
        for (int r = 0; r < 4; r++) {
            const int b = r * 16 + b0;
            float4 v = *reinterpret_cast<const float4*>(x + (size_t)b * DIM + d0 + col);
            tile[col + 0][b] = v.x;
            tile[col + 1][b] = v.y;
            tile[col + 2][b] = v.z;
            tile[col + 3][b] = v.w;
        }
    }
    __syncthreads();

    // ---- transpose phase 2: convert + coalesced fp16 write ----
    {
        const int dd   = t >> 2;
        const int part = t & 3;
        __half2 h[8];
        #pragma unroll
        for (int j = 0; j < 8; j++) {
            h[j] = __floats2half2_rn(tile[dd][part * 16 + 2 * j],
                                     tile[dd][part * 16 + 2 * j + 1]);
        }
        uint4* dst = reinterpret_cast<uint4*>(g_xh + (size_t)(d0 + dd) * 64 + part * 16);
        dst[0] = *reinterpret_cast<uint4*>(&h[0]);
        dst[1] = *reinterpret_cast<uint4*>(&h[4]);
    }
}

// ---------------------------------------------------------------------------
// Kernel 2: gather, bucket split across 2 warps (4 shard lists each).
// Inner loop body is byte-identical to R12 (best measured). Grid = PROJ/4,
// 8 warps/CTA = 2 warps x 4 buckets. Halves per-warp serial chain; doubles
// the number of independent chains in flight.
// ---------------------------------------------------------------------------
__device__ __forceinline__ void accum8(float (&acc)[8], uint4 raw, unsigned rec) {
    const float s = (rec & 1u) ? 1.0f : -1.0f;
    const float2 f0 = __half22float2(*reinterpret_cast<const __half2*>(&raw.x));
    const float2 f1 = __half22float2(*reinterpret_cast<const __half2*>(&raw.y));
    const float2 f2 = __half22float2(*reinterpret_cast<const __half2*>(&raw.z));
    const float2 f3 = __half22float2(*reinterpret_cast<const __half2*>(&raw.w));
    acc[0] = fmaf(s, f0.x, acc[0]);
    acc[1] = fmaf(s, f0.y, acc[1]);
    acc[2] = fmaf(s, f1.x, acc[2]);
    acc[3] = fmaf(s, f1.y, acc[3]);
    acc[4] = fmaf(s, f2.x, acc[4]);
    acc[5] = fmaf(s, f2.y, acc[5]);
    acc[6] = fmaf(s, f3.x, acc[6]);
    acc[7] = fmaf(s, f3.y, acc[7]);
}

__global__ void __launch_bounds__(256)
gather_kernel(float* __restrict__ out) {
    __shared__ float s_res[2][64][4];   // [half][b][bucket-in-CTA]

    const int warp = threadIdx.x >> 5;
    const int lane = threadIdx.x & 31;
    const int bq   = warp >> 1;          // bucket-in-CTA 0..3
    const int half = warp & 1;           // shard half: 0 -> shards 0..3, 1 -> 4..7
    const int p    = blockIdx.x * 4 + bq;
    const int g    = lane >> 3;          // entry group 0..3
    const int sub  = lane & 7;           // batch octet 0..7
    const int suboff = sub << 3;

    const unsigned short* __restrict__ xh = g_xh;

    float acc[8] = {0.f, 0.f, 0.f, 0.f, 0.f, 0.f, 0.f, 0.f};

    #pragma unroll
    for (int ss = 0; ss < NSHARD / 2; ss++) {
        const int s = half * (NSHARD / 2) + ss;
        int count = g_cursor[s * PROJ + p];
        count = (count < BCAPS) ? count : BCAPS;
        const unsigned* __restrict__ ent =
            g_entries + ((size_t)s * PROJ + p) * BCAPS;
        for (int i = g; i < count; i += 4) {
            const unsigned r = ent[i];
            const uint4 a = *reinterpret_cast<const uint4*>(
                xh + ((size_t)(r >> 1) << 6) + suboff);
            accum8(acc, a, r);
        }
    }

    // Reset this warp's 4 shard cursors for the next launch.
    if (lane < NSHARD / 2) g_cursor[(half * (NSHARD / 2) + lane) * PROJ + p] = 0;

    // Reduce the 4 entry-groups (lanes l, l^8, l^16, l^24 share `sub`).
    #pragma unroll
    for (int k = 0; k < 8; k++) {
        acc[k] += __shfl_xor_sync(0xFFFFFFFFu, acc[k], 8);
        acc[k] += __shfl_xor_sync(0xFFFFFFFFu, acc[k], 16);
    }

    if (lane < 8) {
        #pragma unroll
        for (int k = 0; k < 8; k++)
            s_res[half][sub * 8 + k][bq] = acc[k];
    }
    __syncthreads();

    // Merge halves + scale 0.5, coalesced-ish store: thread t -> out[b][p0+pp].
    {
        const int b  = threadIdx.x >> 2;
        const int pp = threadIdx.x & 3;
        const float v = 0.5f * (s_res[0][b][pp] + s_res[1][b][pp]);
        out[(size_t)b * PROJ + blockIdx.x * 4 + pp] = v;
    }
}

extern "C" void kernel_launch(void* const* d_in, const int* in_sizes, int n_in,
                              void* d_out, int out_size) {
    const float* x   = (const float*)d_in[0];
    const int*   idx = (const int*)d_in[1];
    const int*   sgn = (const int*)d_in[2];
    float*       out = (float*)d_out;

    prep_kernel<<<DIM / 64, 256>>>(x, idx, sgn);
    gather_kernel<<<PROJ / 4, 256>>>(out);
}

// round 16
// speedup vs baseline: 1.1352x; 1.1352x over previous
#include <cuda_runtime.h>
#include <cuda_fp16.h>
#include <cstdint>

#define BATCH 64
#define DIM   524288
#define PROJ  8192
#define CVAL  4
#define NSHARD 8
#define BCAPS  128   // per-(shard,bucket) capacity; mean 32, Poisson tail ~1e-40

// ----------------------------- device scratch ------------------------------
__device__ __align__(16) unsigned short g_xh[(size_t)DIM * BATCH]; // fp16 xT[d][b], 64 MB
__device__ __align__(16) unsigned g_entries[(size_t)NSHARD * PROJ * BCAPS]; // 32 MB
__device__ int g_cursor[NSHARD * PROJ];  // zero-init; gather resets after use

// ---------------------------------------------------------------------------
// Kernel 1 (fused, exact R12): every CTA transposes its 64 d-columns AND
// places its own 64 d-rows into the sharded bucket lists.
// ---------------------------------------------------------------------------
__global__ void __launch_bounds__(256)
prep_kernel(const float* __restrict__ x,
            const int* __restrict__ idx, const int* __restrict__ sgn) {
    __shared__ float tile[64][65];

    const int d0 = blockIdx.x * 64;
    const int t  = threadIdx.x;

    // ---- place: threads 0..63, one d each (coalesced int4 reads) ----
    if (t < 64) {
        const int d = d0 + t;
        const int shard = blockIdx.x & (NSHARD - 1);
        const int4 iv = reinterpret_cast<const int4*>(idx)[d];
        const int4 sv = reinterpret_cast<const int4*>(sgn)[d];
        const unsigned rec = (unsigned)d << 1;
        int* cur = g_cursor + shard * PROJ;
        unsigned* ent = g_entries + (size_t)shard * PROJ * BCAPS;
        int p, pos;
        p = iv.x; pos = atomicAdd(&cur[p], 1);
        if (pos < BCAPS) ent[(size_t)p * BCAPS + pos] = rec | sv.x;
        p = iv.y; pos = atomicAdd(&cur[p], 1);
        if (pos < BCAPS) ent[(size_t)p * BCAPS + pos] = rec | sv.y;
        p = iv.z; pos = atomicAdd(&cur[p], 1);
        if (pos < BCAPS) ent[(size_t)p * BCAPS + pos] = rec | sv.z;
        p = iv.w; pos = atomicAdd(&cur[p], 1);
        if (pos < BCAPS) ent[(size_t)p * BCAPS + pos] = rec | sv.w;
    }

    // ---- transpose phase 1: coalesced float4 reads -> smem ----
    {
        const int col = (t & 15) * 4;
        const int b0  = t >> 4;            // 0..15
        #pragma unroll
        for (int r = 0; r < 4; r++) {
            const int b = r * 16 + b0;
            float4 v = *reinterpret_cast<const float4*>(x + (size_t)b * DIM + d0 + col);
            tile[col + 0][b] = v.x;
            tile[col + 1][b] = v.y;
            tile[col + 2][b] = v.z;
            tile[col + 3][b] = v.w;
        }
    }
    __syncthreads();

    // ---- transpose phase 2: convert + coalesced fp16 write ----
    {
        const int dd   = t >> 2;
        const int part = t & 3;
        __half2 h[8];
        #pragma unroll
        for (int j = 0; j < 8; j++) {
            h[j] = __floats2half2_rn(tile[dd][part * 16 + 2 * j],
                                     tile[dd][part * 16 + 2 * j + 1]);
        }
        uint4* dst = reinterpret_cast<uint4*>(g_xh + (size_t)(d0 + dd) * 64 + part * 16);
        dst[0] = *reinterpret_cast<uint4*>(&h[0]);
        dst[1] = *reinterpret_cast<uint4*>(&h[4]);
    }
}

// ---------------------------------------------------------------------------
// Kernel 2: gather (R12 mapping: one warp per bucket), with shard lists
// staged into SMEM via cp.async (double-buffered). One 512B list = one
// cp.async x 32 lanes. Records then come from LDS (29 cyc) instead of L2
// (~250 cyc), breaking the ent->row serial chain at zero register cost.
// ---------------------------------------------------------------------------
#define CP_ASYNC16(dst, src) \
    asm volatile("cp.async.cg.shared.global [%0], [%1], 16;" :: "r"(dst), "l"(src))
#define CP_COMMIT() asm volatile("cp.async.commit_group;" ::: "memory")
#define CP_WAIT(n)  asm volatile("cp.async.wait_group %0;" :: "n"(n) : "memory")

__device__ __forceinline__ void accum8(float (&acc)[8], uint4 raw, unsigned rec) {
    const float s = (rec & 1u) ? 1.0f : -1.0f;
    const float2 f0 = __half22float2(*reinterpret_cast<const __half2*>(&raw.x));
    const float2 f1 = __half22float2(*reinterpret_cast<const __half2*>(&raw.y));
    const float2 f2 = __half22float2(*reinterpret_cast<const __half2*>(&raw.z));
    const float2 f3 = __half22float2(*reinterpret_cast<const __half2*>(&raw.w));
    acc[0] = fmaf(s, f0.x, acc[0]);
    acc[1] = fmaf(s, f0.y, acc[1]);
    acc[2] = fmaf(s, f1.x, acc[2]);
    acc[3] = fmaf(s, f1.y, acc[3]);
    acc[4] = fmaf(s, f2.x, acc[4]);
    acc[5] = fmaf(s, f2.y, acc[5]);
    acc[6] = fmaf(s, f3.x, acc[6]);
    acc[7] = fmaf(s, f3.y, acc[7]);
}

__global__ void __launch_bounds__(256, 8)
gather_kernel(float* __restrict__ out) {
    __shared__ __align__(16) unsigned s_rec[8][2][BCAPS];  // 8 warps x 2 x 512B = 8 KB
    __shared__ int s_cnt[8][NSHARD];
    __shared__ float s_res[64][8];

    const int warp = threadIdx.x >> 5;
    const int lane = threadIdx.x & 31;
    const int p    = blockIdx.x * 8 + warp;
    const int g    = lane >> 3;      // entry group 0..3
    const int sub  = lane & 7;       // batch octet 0..7
    const int suboff = sub << 3;

    const unsigned short* __restrict__ xh = g_xh;

    // Counts -> smem (lanes 0..7, one shard each).
    if (lane < NSHARD) {
        int c = g_cursor[lane * PROJ + p];
        s_cnt[warp][lane] = (c < BCAPS) ? c : BCAPS;
    }
    __syncwarp();

    // Stage shard 0 (each lane copies 16B; 32 lanes = full 512B list).
    {
        const uint32_t dst = (uint32_t)__cvta_generic_to_shared(&s_rec[warp][0][lane * 4]);
        const void* src = g_entries + ((size_t)0 * PROJ + p) * BCAPS + lane * 4;
        CP_ASYNC16(dst, src);
        CP_COMMIT();
    }

    float acc[8] = {0.f, 0.f, 0.f, 0.f, 0.f, 0.f, 0.f, 0.f};

    #pragma unroll
    for (int s = 0; s < NSHARD; s++) {
        if (s < NSHARD - 1) {
            const uint32_t dst =
                (uint32_t)__cvta_generic_to_shared(&s_rec[warp][(s + 1) & 1][lane * 4]);
            const void* src = g_entries + ((size_t)(s + 1) * PROJ + p) * BCAPS + lane * 4;
            CP_ASYNC16(dst, src);
            CP_COMMIT();
            CP_WAIT(1);     // buffer s is complete
        } else {
            CP_WAIT(0);
        }
        __syncwarp();

        const int count = s_cnt[warp][s];
        const unsigned* ent = s_rec[warp][s & 1];
        for (int i = g; i < count; i += 4) {
            const unsigned r = ent[i];                 // LDS, 29 cyc
            const uint4 a = *reinterpret_cast<const uint4*>(
                xh + ((size_t)(r >> 1) << 6) + suboff);
            accum8(acc, a, r);
        }
        __syncwarp();       // all lanes done reading before buffer reuse
    }

    // Reset this bucket's shard cursors for the next launch.
    if (lane < NSHARD) g_cursor[lane * PROJ + p] = 0;

    // Reduce the 4 entry-groups (lanes l, l^8, l^16, l^24 share `sub`).
    #pragma unroll
    for (int k = 0; k < 8; k++) {
        acc[k] += __shfl_xor_sync(0xFFFFFFFFu, acc[k], 8);
        acc[k] += __shfl_xor_sync(0xFFFFFFFFu, acc[k], 16);
    }

    if (lane < 8) {
        #pragma unroll
        for (int k = 0; k < 8; k++)
            s_res[sub * 8 + k][warp] = 0.5f * acc[k];   // scale 1/sqrt(4)
    }
    __syncthreads();

    // Coalesced store: thread t writes float2 of out[b][p0 + part*2].
    {
        const int b    = threadIdx.x >> 2;
        const int part = threadIdx.x & 3;
        float2 v = make_float2(s_res[b][part * 2], s_res[b][part * 2 + 1]);
        *reinterpret_cast<float2*>(out + (size_t)b * PROJ + blockIdx.x * 8 + part * 2) = v;
    }
}

extern "C" void kernel_launch(void* const* d_in, const int* in_sizes, int n_in,
                              void* d_out, int out_size) {
    const float* x   = (const float*)d_in[0];
    const int*   idx = (const int*)d_in[1];
    const int*   sgn = (const int*)d_in[2];
    float*       out = (float*)d_out;

    prep_kernel<<<DIM / 64, 256>>>(x, idx, sgn);
    gather_kernel<<<PROJ / 8, 256>>>(out);
}

// round 17
// speedup vs baseline: 1.2378x; 1.0904x over previous
#include <cuda_runtime.h>
#include <cuda_fp16.h>
#include <cstdint>

#define BATCH 64
#define DIM   524288
#define PROJ  8192
#define CVAL  4
#define NSHARD 8
#define BCAPS  128   // per-(shard,bucket) capacity; mean 32, Poisson tail ~1e-40

// ----------------------------- device scratch ------------------------------
__device__ __align__(16) unsigned short g_xh[(size_t)DIM * BATCH]; // fp16 xT[d][b], 64 MB
__device__ __align__(16) unsigned g_entries[(size_t)NSHARD * PROJ * BCAPS]; // 32 MB
__device__ int g_cursor[NSHARD * PROJ];  // zero-init; gather resets after use

// ---------------------------------------------------------------------------
// Kernel 1 (fused, exact R12): every CTA transposes its 64 d-columns AND
// places its own 64 d-rows into the sharded bucket lists.
// ---------------------------------------------------------------------------
__global__ void __launch_bounds__(256)
prep_kernel(const float* __restrict__ x,
            const int* __restrict__ idx, const int* __restrict__ sgn) {
    __shared__ float tile[64][65];

    const int d0 = blockIdx.x * 64;
    const int t  = threadIdx.x;

    // ---- place: threads 0..63, one d each (coalesced int4 reads) ----
    if (t < 64) {
        const int d = d0 + t;
        const int shard = blockIdx.x & (NSHARD - 1);
        const int4 iv = reinterpret_cast<const int4*>(idx)[d];
        const int4 sv = reinterpret_cast<const int4*>(sgn)[d];
        const unsigned rec = (unsigned)d << 1;
        int* cur = g_cursor + shard * PROJ;
        unsigned* ent = g_entries + (size_t)shard * PROJ * BCAPS;
        int p, pos;
        p = iv.x; pos = atomicAdd(&cur[p], 1);
        if (pos < BCAPS) ent[(size_t)p * BCAPS + pos] = rec | sv.x;
        p = iv.y; pos = atomicAdd(&cur[p], 1);
        if (pos < BCAPS) ent[(size_t)p * BCAPS + pos] = rec | sv.y;
        p = iv.z; pos = atomicAdd(&cur[p], 1);
        if (pos < BCAPS) ent[(size_t)p * BCAPS + pos] = rec | sv.z;
        p = iv.w; pos = atomicAdd(&cur[p], 1);
        if (pos < BCAPS) ent[(size_t)p * BCAPS + pos] = rec | sv.w;
    }

    // ---- transpose phase 1: coalesced float4 reads -> smem ----
    {
        const int col = (t & 15) * 4;
        const int b0  = t >> 4;            // 0..15
        #pragma unroll
        for (int r = 0; r < 4; r++) {
            const int b = r * 16 + b0;
            float4 v = *reinterpret_cast<const float4*>(x + (size_t)b * DIM + d0 + col);
            tile[col + 0][b] = v.x;
            tile[col + 1][b] = v.y;
            tile[col + 2][b] = v.z;
            tile[col + 3][b] = v.w;
        }
    }
    __syncthreads();

    // ---- transpose phase 2: convert + coalesced fp16 write ----
    {
        const int dd   = t >> 2;
        const int part = t & 3;
        __half2 h[8];
        #pragma unroll
        for (int j = 0; j < 8; j++) {
            h[j] = __floats2half2_rn(tile[dd][part * 16 + 2 * j],
                                     tile[dd][part * 16 + 2 * j + 1]);
        }
        uint4* dst = reinterpret_cast<uint4*>(g_xh + (size_t)(d0 + dd) * 64 + part * 16);
        dst[0] = *reinterpret_cast<uint4*>(&h[0]);
        dst[1] = *reinterpret_cast<uint4*>(&h[4]);
    }
}

// ---------------------------------------------------------------------------
// Kernel 2: gather. cp.async-staged shard lists (R16) + x4-batched row loads
// (R5's proven shape): 4 LDS records, then 4 back-to-back row LDGs (MLP=4),
// tail via the simple loop. One warp per bucket; regs pinned via
// __launch_bounds__(256, 8).
// ---------------------------------------------------------------------------
#define CP_ASYNC16(dst, src) \
    asm volatile("cp.async.cg.shared.global [%0], [%1], 16;" :: "r"(dst), "l"(src))
#define CP_COMMIT() asm volatile("cp.async.commit_group;" ::: "memory")
#define CP_WAIT(n)  asm volatile("cp.async.wait_group %0;" :: "n"(n) : "memory")

__device__ __forceinline__ void accum8(float (&acc)[8], uint4 raw, unsigned rec) {
    const float s = (rec & 1u) ? 1.0f : -1.0f;
    const float2 f0 = __half22float2(*reinterpret_cast<const __half2*>(&raw.x));
    const float2 f1 = __half22float2(*reinterpret_cast<const __half2*>(&raw.y));
    const float2 f2 = __half22float2(*reinterpret_cast<const __half2*>(&raw.z));
    const float2 f3 = __half22float2(*reinterpret_cast<const __half2*>(&raw.w));
    acc[0] = fmaf(s, f0.x, acc[0]);
    acc[1] = fmaf(s, f0.y, acc[1]);
    acc[2] = fmaf(s, f1.x, acc[2]);
    acc[3] = fmaf(s, f1.y, acc[3]);
    acc[4] = fmaf(s, f2.x, acc[4]);
    acc[5] = fmaf(s, f2.y, acc[5]);
    acc[6] = fmaf(s, f3.x, acc[6]);
    acc[7] = fmaf(s, f3.y, acc[7]);
}

__global__ void __launch_bounds__(256, 8)
gather_kernel(float* __restrict__ out) {
    __shared__ __align__(16) unsigned s_rec[8][2][BCAPS];  // 8 warps x 2 x 512B = 8 KB
    __shared__ int s_cnt[8][NSHARD];
    __shared__ float s_res[64][8];

    const int warp = threadIdx.x >> 5;
    const int lane = threadIdx.x & 31;
    const int p    = blockIdx.x * 8 + warp;
    const int g    = lane >> 3;      // entry group 0..3
    const int sub  = lane & 7;       // batch octet 0..7
    const int suboff = sub << 3;

    const unsigned short* __restrict__ xh = g_xh;

    // Counts -> smem (lanes 0..7, one shard each).
    if (lane < NSHARD) {
        int c = g_cursor[lane * PROJ + p];
        s_cnt[warp][lane] = (c < BCAPS) ? c : BCAPS;
    }
    __syncwarp();

    // Stage shard 0 (each lane copies 16B; 32 lanes = full 512B list).
    {
        const uint32_t dst = (uint32_t)__cvta_generic_to_shared(&s_rec[warp][0][lane * 4]);
        const void* src = g_entries + ((size_t)0 * PROJ + p) * BCAPS + lane * 4;
        CP_ASYNC16(dst, src);
        CP_COMMIT();
    }

    float acc[8] = {0.f, 0.f, 0.f, 0.f, 0.f, 0.f, 0.f, 0.f};

    #pragma unroll
    for (int s = 0; s < NSHARD; s++) {
        if (s < NSHARD - 1) {
            const uint32_t dst =
                (uint32_t)__cvta_generic_to_shared(&s_rec[warp][(s + 1) & 1][lane * 4]);
            const void* src = g_entries + ((size_t)(s + 1) * PROJ + p) * BCAPS + lane * 4;
            CP_ASYNC16(dst, src);
            CP_COMMIT();
            CP_WAIT(1);     // buffer s is complete
        } else {
            CP_WAIT(0);
        }
        __syncwarp();

        const int count = s_cnt[warp][s];
        const unsigned* ent = s_rec[warp][s & 1];

        int i = g;
        // x4 batch: 4 LDS records, then 4 back-to-back row LDGs (MLP=4).
        for (; i + 12 < count; i += 16) {
            const unsigned r0 = ent[i];
            const unsigned r1 = ent[i + 4];
            const unsigned r2 = ent[i + 8];
            const unsigned r3 = ent[i + 12];
            const uint4 a0 = *reinterpret_cast<const uint4*>(xh + ((size_t)(r0 >> 1) << 6) + suboff);
            const uint4 a1 = *reinterpret_cast<const uint4*>(xh + ((size_t)(r1 >> 1) << 6) + suboff);
            const uint4 a2 = *reinterpret_cast<const uint4*>(xh + ((size_t)(r2 >> 1) << 6) + suboff);
            const uint4 a3 = *reinterpret_cast<const uint4*>(xh + ((size_t)(r3 >> 1) << 6) + suboff);
            accum8(acc, a0, r0);
            accum8(acc, a1, r1);
            accum8(acc, a2, r2);
            accum8(acc, a3, r3);
        }
        for (; i < count; i += 4) {
            const unsigned r = ent[i];
            const uint4 a = *reinterpret_cast<const uint4*>(
                xh + ((size_t)(r >> 1) << 6) + suboff);
            accum8(acc, a, r);
        }
        __syncwarp();       // all lanes done reading before buffer reuse
    }

    // Reset this bucket's shard cursors for the next launch.
    if (lane < NSHARD) g_cursor[lane * PROJ + p] = 0;

    // Reduce the 4 entry-groups (lanes l, l^8, l^16, l^24 share `sub`).
    #pragma unroll
    for (int k = 0; k < 8; k++) {
        acc[k] += __shfl_xor_sync(0xFFFFFFFFu, acc[k], 8);
        acc[k] += __shfl_xor_sync(0xFFFFFFFFu, acc[k], 16);
    }

    if (lane < 8) {
        #pragma unroll
        for (int k = 0; k < 8; k++)
            s_res[sub * 8 + k][warp] = 0.5f * acc[k];   // scale 1/sqrt(4)
    }
    __syncthreads();

    // Coalesced store: thread t writes float2 of out[b][p0 + part*2].
    {
        const int b    = threadIdx.x >> 2;
        const int part = threadIdx.x & 3;
        float2 v = make_float2(s_res[b][part * 2], s_res[b][part * 2 + 1]);
        *reinterpret_cast<float2*>(out + (size_t)b * PROJ + blockIdx.x * 8 + part * 2) = v;
    }
}

extern "C" void kernel_launch(void* const* d_in, const int* in_sizes, int n_in,
                              void* d_out, int out_size) {
    const float* x   = (const float*)d_in[0];
    const int*   idx = (const int*)d_in[1];
    const int*   sgn = (const int*)d_in[2];
    float*       out = (float*)d_out;

    prep_kernel<<<DIM / 64, 256>>>(x, idx, sgn);
    gather_kernel<<<PROJ / 8, 256>>>(out);
}